// round 1
// baseline (speedup 1.0000x reference)
#include <cuda_runtime.h>
#include <math.h>

#define BB 128
#define TT 512
#define II 512
#define HH 512
#define H3 1536
#define KK 512

// ---------------- scratch (device globals: allocation-free) ----------------
__device__ float g_xlin[(size_t)BB * TT * H3];   // [B,T,3H]  402.7 MB
__device__ float g_wt[KK * H3];                  // Wh transposed: wt[k][n] = Wh[n][k]
__device__ float g_hbuf[2][BB * HH];             // ping-pong hidden state

// ---------------- small helpers ----------------
__global__ void copy_f(const float* __restrict__ src, float* __restrict__ dst, int n) {
    int i = blockIdx.x * blockDim.x + threadIdx.x;
    if (i < n) dst[i] = src[i];
}

// Wh [1536,512] -> wt [512,1536]
__global__ void transpose_wh(const float* __restrict__ wh, float* __restrict__ wt) {
    __shared__ float tile[32][33];
    int kb = blockIdx.x * 32;   // k base (512/32 = 16)
    int nb = blockIdx.y * 32;   // n base (1536/32 = 48)
    int tx = threadIdx.x;       // 0..31
    int ty = threadIdx.y;       // 0..7
#pragma unroll
    for (int i = 0; i < 32; i += 8)
        tile[ty + i][tx] = wh[(size_t)(nb + ty + i) * KK + kb + tx];
    __syncthreads();
#pragma unroll
    for (int i = 0; i < 32; i += 8)
        wt[(size_t)(kb + ty + i) * H3 + nb + tx] = tile[tx][ty + i];
}

// ---------------- Phase 1: x_lin = x @ Wx^T + bx ----------------
// M = 65536, N = 1536, K = 512. CTA tile 128x128, BK=16, 256 threads, 8x8 per thread.
__global__ void __launch_bounds__(256, 2) sgemm_xlin(
    const float* __restrict__ A,    // x  [M,K]
    const float* __restrict__ Bw,   // Wx [N,K]
    const float* __restrict__ bias, // bx [N]
    float* __restrict__ C)          // [M,N]
{
    __shared__ float As[16][128];
    __shared__ float Bs[16][128];

    const int tid = threadIdx.x;
    const int m0 = blockIdx.y * 128;
    const int n0 = blockIdx.x * 128;

    // global-load mapping: 512 float4 per tile per matrix, 2 per thread
    const int lrow = tid >> 2;      // 0..63
    const int lkq  = tid & 3;       // 0..3 (float4 within 16-wide k)
    const float* Ap = A  + (size_t)(m0 + lrow) * KK + lkq * 4;
    const float* Bp = Bw + (size_t)(n0 + lrow) * KK + lkq * 4;

    const int tn = tid & 15;        // 0..15 (n-tile)
    const int tm = tid >> 4;        // 0..15 (m-tile)

    float acc[8][8];
#pragma unroll
    for (int i = 0; i < 8; i++)
#pragma unroll
        for (int j = 0; j < 8; j++) acc[i][j] = 0.f;

    float4 ra0, ra1, rb0, rb1;

    auto ldtile = [&](int kt) {
        ra0 = *(const float4*)(Ap + kt * 16);
        ra1 = *(const float4*)(Ap + (size_t)64 * KK + kt * 16);
        rb0 = *(const float4*)(Bp + kt * 16);
        rb1 = *(const float4*)(Bp + (size_t)64 * KK + kt * 16);
    };
    auto sttile = [&]() {
        As[lkq * 4 + 0][lrow] = ra0.x; As[lkq * 4 + 1][lrow] = ra0.y;
        As[lkq * 4 + 2][lrow] = ra0.z; As[lkq * 4 + 3][lrow] = ra0.w;
        As[lkq * 4 + 0][lrow + 64] = ra1.x; As[lkq * 4 + 1][lrow + 64] = ra1.y;
        As[lkq * 4 + 2][lrow + 64] = ra1.z; As[lkq * 4 + 3][lrow + 64] = ra1.w;
        Bs[lkq * 4 + 0][lrow] = rb0.x; Bs[lkq * 4 + 1][lrow] = rb0.y;
        Bs[lkq * 4 + 2][lrow] = rb0.z; Bs[lkq * 4 + 3][lrow] = rb0.w;
        Bs[lkq * 4 + 0][lrow + 64] = rb1.x; Bs[lkq * 4 + 1][lrow + 64] = rb1.y;
        Bs[lkq * 4 + 2][lrow + 64] = rb1.z; Bs[lkq * 4 + 3][lrow + 64] = rb1.w;
    };
    auto compute = [&]() {
#pragma unroll
        for (int k = 0; k < 16; k++) {
            float a[8], b[8];
#pragma unroll
            for (int i = 0; i < 8; i++) a[i] = As[k][tm * 8 + i];
#pragma unroll
            for (int j = 0; j < 8; j++) b[j] = Bs[k][tn * 8 + j];
#pragma unroll
            for (int i = 0; i < 8; i++)
#pragma unroll
                for (int j = 0; j < 8; j++) acc[i][j] = fmaf(a[i], b[j], acc[i][j]);
        }
    };

    ldtile(0);
    sttile();
    __syncthreads();
    const int NT = KK / 16;
    for (int kt = 1; kt < NT; kt++) {
        ldtile(kt);       // LDGs fly while we compute on current smem tile
        compute();
        __syncthreads();
        sttile();
        __syncthreads();
    }
    compute();

    // epilogue: + bias, vectorized stores
    float bv[8];
#pragma unroll
    for (int j = 0; j < 8; j++) bv[j] = bias[n0 + tn * 8 + j];
#pragma unroll
    for (int i = 0; i < 8; i++) {
        size_t row = (size_t)(m0 + tm * 8 + i);
        float4 c0 = make_float4(acc[i][0] + bv[0], acc[i][1] + bv[1],
                                acc[i][2] + bv[2], acc[i][3] + bv[3]);
        float4 c1 = make_float4(acc[i][4] + bv[4], acc[i][5] + bv[5],
                                acc[i][6] + bv[6], acc[i][7] + bv[7]);
        float4* cp = (float4*)(C + row * H3 + n0 + tn * 8);
        cp[0] = c0;
        cp[1] = c1;
    }
}

// ---------------- Phase 2: one GRU timestep ----------------
// grid (16 unit-tiles of 32, 8 batch-tiles of 16), 256 threads.
// thread = (unit u, batch pair). Each thread computes z/r/n dots over K=512
// and finishes the gating locally — no cross-thread communication needed.
__global__ void __launch_bounds__(256, 1) gru_step(
    const float* __restrict__ xlin,  // [B,T,3H]
    const float* __restrict__ wt,    // [K,3H] transposed Wh
    const float* __restrict__ h_in,  // [B,H]
    float* __restrict__ h_out,       // [B,H]
    float* __restrict__ y,           // [B,T,H]
    int t)
{
    __shared__ float hs[16 * HH];    // 32 KB h tile

    const int tid = threadIdx.x;
    const int u   = blockIdx.x * 32 + (tid & 31);
    const int wg  = tid >> 5;        // 0..7 -> batch pair
    const int b0  = blockIdx.y * 16;

    // coalesced load of 16x512 h tile (8192 floats = 2048 float4)
    {
        const float4* hin4 = (const float4*)(h_in + (size_t)b0 * HH);
        float4* hs4 = (float4*)hs;
#pragma unroll
        for (int i = 0; i < 8; i++) hs4[tid + i * 256] = hin4[tid + i * 256];
    }
    __syncthreads();

    const int bl0 = wg * 2;
    const float* h0p = hs + bl0 * HH;
    const float* h1p = hs + (bl0 + 1) * HH;
    const float* wp  = wt + u;

    float az0 = 0.f, ar0 = 0.f, an0 = 0.f;
    float az1 = 0.f, ar1 = 0.f, an1 = 0.f;

#pragma unroll 8
    for (int k = 0; k < KK; k++) {
        float wz = wp[0];
        float wr = wp[512];
        float wn = wp[1024];
        float ha = h0p[k];
        float hb = h1p[k];
        az0 = fmaf(ha, wz, az0); ar0 = fmaf(ha, wr, ar0); an0 = fmaf(ha, wn, an0);
        az1 = fmaf(hb, wz, az1); ar1 = fmaf(hb, wr, ar1); an1 = fmaf(hb, wn, an1);
        wp += H3;
    }

#pragma unroll
    for (int e = 0; e < 2; e++) {
        float az = e ? az1 : az0;
        float ar = e ? ar1 : ar0;
        float an = e ? an1 : an0;
        int b = b0 + bl0 + e;
        const float* xl = xlin + ((size_t)b * TT + t) * H3;
        float xz = xl[u];
        float xr = xl[u + 512];
        float xn = xl[u + 1024];
        float hold = hs[(bl0 + e) * HH + u];
        float z = 1.f / (1.f + expf(-(xz + az)));
        float r = 1.f / (1.f + expf(-(xr + ar)));
        float n = tanhf(xn + r * an);
        float hn = (1.f - z) * n + z * hold;
        h_out[(size_t)b * HH + u] = hn;
        y[((size_t)b * TT + t) * HH + u] = hn;
    }
}

// ---------------- launch ----------------
extern "C" void kernel_launch(void* const* d_in, const int* in_sizes, int n_in,
                              void* d_out, int out_size) {
    const float* x  = (const float*)d_in[0];  // [B,T,I]
    const float* h0 = (const float*)d_in[1];  // [B,H]
    const float* Wx = (const float*)d_in[2];  // [3H,I]
    const float* bx = (const float*)d_in[3];  // [3H]
    const float* Wh = (const float*)d_in[4];  // [3H,H]
    float* out = (float*)d_out;

    float *xlin, *wt, *hbuf;
    cudaGetSymbolAddress((void**)&xlin, g_xlin);
    cudaGetSymbolAddress((void**)&wt, g_wt);
    cudaGetSymbolAddress((void**)&hbuf, g_hbuf);

    // h state init + weight transpose
    copy_f<<<(BB * HH + 255) / 256, 256>>>(h0, hbuf, BB * HH);
    transpose_wh<<<dim3(KK / 32, H3 / 32), dim3(32, 8)>>>(Wh, wt);

    // phase 1: input projections for all timesteps
    sgemm_xlin<<<dim3(H3 / 128, (BB * TT) / 128), 256>>>(x, Wx, bx, xlin);

    // phase 2: 512 sequential steps (ping-pong h buffers)
    for (int t = 0; t < TT; t++) {
        const float* hin = hbuf + (size_t)(t & 1) * BB * HH;
        float* hout      = hbuf + (size_t)((t + 1) & 1) * BB * HH;
        gru_step<<<dim3(HH / 32, BB / 16), 256>>>(xlin, wt, hin, hout, out, t);
    }

    // h_final (recurrence ends with state in buffer 0 since T is even)
    if (out_size >= (int)((size_t)BB * TT * HH + BB * HH)) {
        copy_f<<<(BB * HH + 255) / 256, 256>>>(hbuf, out + (size_t)BB * TT * HH,
                                               BB * HH);
    }
}